// round 7
// baseline (speedup 1.0000x reference)
#include <cuda_runtime.h>
#include <cuda_bf16.h>

// Problem constants (fixed by the reference)
#define GRID_NX   48
#define GRID_NY   48
#define GRID_NZ   48
#define N_GRID    (GRID_NX * GRID_NY * GRID_NZ)   // 110592
#define SPACING   0.5f
#define A_MAX     800
#define NG        6
#define MAX_PAIRS (A_MAX * NG)                    // 4800

// Cull threshold: drop pair for a tile when |c|*min_d2 > T  (contribution < 2^-24 * w)
#define T_CUT     24.0f

// Tile geometry: 8 x 8 x 4 grid points per tile (432 tiles)
#define TILE_X 8
#define TILE_Y 8
#define TILE_Z 4
#define NBX (GRID_NX / TILE_X)   // 6
#define NBY (GRID_NY / TILE_Y)   // 6
#define NBZ (GRID_NZ / TILE_Z)   // 12
#define N_TILES (NBX * NBY * NBZ)

#define NWARP  8                 // pair-range partitions (one warp each)
#define CHUNK  128               // pairs culled per warp-chunk

// Pair tables (scratch: __device__ globals, no allocation)
__device__ float4 g_cull[MAX_PAIRS];    // px, py, pz, d2cut (-1 => inactive)
__device__ float4 g_pcA[MAX_PAIRS];     // px, py, pz, c (= bw * log2e)
__device__ float4 g_pcB[MAX_PAIRS];     // w, q (= 2^(c/2)), c4 (= 0.25c), 0

__device__ __forceinline__ float ex2f(float x) {
    float r;
    asm("ex2.approx.f32 %0, %1;" : "=f"(r) : "f"(x));
    return r;
}

// ---------------------------------------------------------------------------
// Kernel 1: build pair tables, fully parallel (one thread per pair).
// Inactive pairs get d2cut = -1 and are dropped by the tile cull in kernel 2
// (md2 >= 0 > -1). Survivor order == original pair order => deterministic.
// ---------------------------------------------------------------------------
__global__ __launch_bounds__(128)
void build_pairs(const float* __restrict__ X,
                 const float* __restrict__ aw,
                 const float* __restrict__ bw,
                 const int*   __restrict__ elements,
                 const int*   __restrict__ C_expand,
                 int npairs)
{
    const float LOG2E = 1.4426950408889634f;
    int j = blockIdx.x * 128 + threadIdx.x;
    if (j >= npairs) return;
    int a = j / NG;

    bool act = (elements[a] != 5) && (C_expand[a] == 1);
    float c = bw[j] * LOG2E;          // c < 0
    float w = aw[j];
    float px = X[a * 3 + 0];
    float py = X[a * 3 + 1];
    float pz = X[a * 3 + 2];

    g_cull[j] = make_float4(px, py, pz, act ? (T_CUT / (-c)) : -1.0f);
    g_pcA[j]  = make_float4(px, py, pz, c);
    g_pcB[j]  = make_float4(w, ex2f(0.5f * c), 0.25f * c, 0.0f);
}

// ---------------------------------------------------------------------------
// Kernel 2: density, fused. One 256-thread block per tile; warp w handles
// pair eighth w independently (cull + accumulate), then a deterministic
// fixed-order intra-block reduction and a direct coalesced store.
//
// Per-warp math: each lane owns one x-row (8 points); TWO-ANCHOR exp2
// recurrence (anchors at x-index 0 and 4, each point <= 1.5 A from its
// anchor => anchor magnitude >= 2^-111, no denormal flush):
//   r_i = 2^(c*dx_i + 0.25c),  r_{i+1} = r_i * q,  q = 2^(c/2)
// ---------------------------------------------------------------------------
__global__ __launch_bounds__(256)
void density_kernel(int npairs, float* __restrict__ out)
{
    __shared__ float4 s_pa[NWARP][CHUNK];             // px, py, pz, c
    __shared__ float4 s_pb[NWARP][CHUNK];             // w, q, c4
    __shared__ float  s_acc[NWARP][32][TILE_X + 1];   // +1: bank padding

    int tid  = threadIdx.x;
    int lane = tid & 31;
    int wid  = tid >> 5;
    int bid  = blockIdx.x;
    int bx = bid % NBX;
    int by = (bid / NBX) % NBY;
    int bz = bid / (NBX * NBY);

    // Tile AABB in real coordinates
    float x_lo = (float)(bx * TILE_X) * SPACING;
    float y_lo = (float)(by * TILE_Y) * SPACING;
    float z_lo = (float)(bz * TILE_Z) * SPACING;
    float x_hi = x_lo + (float)(TILE_X - 1) * SPACING;
    float y_hi = y_lo + (float)(TILE_Y - 1) * SPACING;
    float z_hi = z_lo + (float)(TILE_Z - 1) * SPACING;

    // This lane's x-row: lane -> (ty in 0..7, tz in 0..3)
    int ty = lane & 7;
    int tz = lane >> 3;
    float gx0 = x_lo;
    float gy  = y_lo + (float)ty * SPACING;
    float gz  = z_lo + (float)tz * SPACING;

    // This warp's pair range
    int p_beg = (npairs * wid) / NWARP;
    int p_end = (npairs * (wid + 1)) / NWARP;

    float acc[TILE_X];
#pragma unroll
    for (int i = 0; i < TILE_X; i++) acc[i] = 0.0f;

    for (int c0 = p_beg; c0 < p_end; c0 += CHUNK) {
        int cend = p_end - c0;
        if (cend > CHUNK) cend = CHUNK;

        // ---- Fused cull + order-preserving compaction (per warp)
        int nsurv = 0;
#pragma unroll
        for (int r = 0; r < CHUNK / 32; r++) {
            int jl = r * 32 + lane;
            int j  = c0 + jl;
            bool sv = false;
            if (jl < cend) {
                float4 cd = g_cull[j];
                float dx = fmaxf(fmaxf(x_lo - cd.x, cd.x - x_hi), 0.0f);
                float dy = fmaxf(fmaxf(y_lo - cd.y, cd.y - y_hi), 0.0f);
                float dz = fmaxf(fmaxf(z_lo - cd.z, cd.z - z_hi), 0.0f);
                float md2 = fmaf(dx, dx, fmaf(dy, dy, dz * dz));
                sv = (md2 <= cd.w);
            }
            unsigned m = __ballot_sync(0xffffffffu, sv);
            if (sv) {
                int pos = nsurv + __popc(m & ((1u << lane) - 1u));
                s_pa[wid][pos] = g_pcA[j];
                s_pb[wid][pos] = g_pcB[j];
            }
            nsurv += __popc(m);
        }
        __syncwarp();

        // ---- Accumulate with two-anchor recurrence
        for (int s = 0; s < nsurv; s++) {
            float4 p = s_pa[wid][s];   // px, py, pz, c
            float4 v = s_pb[wid][s];   // w, q, c4
            float dy = gy - p.y;
            float dz = gz - p.z;
            float s2 = fmaf(dy, dy, dz * dz);
            float dx0 = gx0 - p.x;
            float dx4 = dx0 + 2.0f;

            float e  = v.x * ex2f(fmaf(dx0, dx0, s2) * p.w);   // anchor @ x0
            float e4 = v.x * ex2f(fmaf(dx4, dx4, s2) * p.w);   // anchor @ x4
            float r  = ex2f(fmaf(p.w, dx0, v.z));              // ratio chain

            acc[0] += e;
            e *= r; r *= v.y; acc[1] += e;
            e *= r; r *= v.y; acc[2] += e;
            e *= r; r *= v.y; acc[3] += e;
            r *= v.y;                       // r now = r4
            acc[4] += e4;
            e4 *= r; r *= v.y; acc[5] += e4;
            e4 *= r; r *= v.y; acc[6] += e4;
            e4 *= r;           acc[7] += e4;
        }
        __syncwarp();   // protect this warp's shared chunk before refill
    }

    // ---- Deposit per-warp accumulators
#pragma unroll
    for (int i = 0; i < TILE_X; i++)
        s_acc[wid][lane][i] = acc[i];
    __syncthreads();

    // ---- Deterministic fixed-order reduction + direct coalesced store.
    // Thread t handles grid point: row l = t>>3 (32 rows), x index i = t&7.
    int l = tid >> 3;
    int i = tid & 7;
    int rty = l & 7;
    int rtz = l >> 3;
    int g0 = (bz * TILE_Z + rtz) * (GRID_NX * GRID_NY)
           + (by * TILE_Y + rty) * GRID_NX
           + bx * TILE_X + i;

    float r = s_acc[0][l][i];
#pragma unroll
    for (int w = 1; w < NWARP; w++)
        r += s_acc[w][l][i];
    out[g0] = r;
}

// ---------------------------------------------------------------------------
// Launch. Inputs (metadata order): X[800*3] f32, aw[800*6] f32, bw[800*6] f32,
// elements[800] i32, C_expand[800] i32, real_grid[110592*3] f32 (unused).
// Output: density[110592] f32.
// ---------------------------------------------------------------------------
extern "C" void kernel_launch(void* const* d_in, const int* in_sizes, int n_in,
                              void* d_out, int out_size)
{
    const float* X        = (const float*)d_in[0];
    const float* aw       = (const float*)d_in[1];
    const float* bw       = (const float*)d_in[2];
    const int*   elements = (const int*)d_in[3];
    const int*   C_expand = (const int*)d_in[4];
    float*       out      = (float*)d_out;

    int n_atoms = in_sizes[3];
    int npairs  = n_atoms * NG;

    build_pairs<<<(npairs + 127) / 128, 128>>>(X, aw, bw, elements, C_expand,
                                               npairs);

    density_kernel<<<N_TILES, 256>>>(npairs, out);
}

// round 8
// speedup vs baseline: 1.1223x; 1.1223x over previous
#include <cuda_runtime.h>
#include <cuda_bf16.h>

// Problem constants (fixed by the reference)
#define GRID_NX   48
#define GRID_NY   48
#define GRID_NZ   48
#define N_GRID    (GRID_NX * GRID_NY * GRID_NZ)   // 110592
#define SPACING   0.5f
#define A_MAX     800
#define NG        6
#define MAX_PAIRS (A_MAX * NG)                    // 4800

// Cull threshold: drop pair for a tile when |c|*min_d2 > T  (contribution < 2^-18 * w)
#define T_CUT     18.0f

// Tile geometry: 8 x 8 x 4 grid points per tile (432 tiles)
#define TILE_X 8
#define TILE_Y 8
#define TILE_Z 4
#define NBX (GRID_NX / TILE_X)   // 6
#define NBY (GRID_NY / TILE_Y)   // 6
#define NBZ (GRID_NZ / TILE_Z)   // 12
#define N_TILES (NBX * NBY * NBZ)

#define NWARP  8                 // pair-range partitions (one warp each)
#define CHUNK  128               // pairs culled per warp-chunk

// Pair tables (scratch: __device__ globals, no allocation)
__device__ float4 g_cull[MAX_PAIRS];    // px, py, pz, d2cut (-1 => inactive)
__device__ float4 g_pcA[MAX_PAIRS];     // px, py, pz, c (= bw * log2e)
__device__ float4 g_pcB[MAX_PAIRS];     // w, q (= 2^(c/2)), c4 (= c/4), q4 (= 2^(2c))

__device__ __forceinline__ float ex2f(float x) {
    float r;
    asm("ex2.approx.f32 %0, %1;" : "=f"(r) : "f"(x));
    return r;
}

// Packed f32x2 helpers (Blackwell)
__device__ __forceinline__ unsigned long long pk(float lo, float hi) {
    unsigned long long r;
    asm("mov.b64 %0, {%1, %2};" : "=l"(r) : "f"(lo), "f"(hi));
    return r;
}
__device__ __forceinline__ void unpk(float& lo, float& hi, unsigned long long v) {
    asm("mov.b64 {%0, %1}, %2;" : "=f"(lo), "=f"(hi) : "l"(v));
}
__device__ __forceinline__ unsigned long long mul2(unsigned long long a,
                                                   unsigned long long b) {
    unsigned long long r;
    asm("mul.rn.f32x2 %0, %1, %2;" : "=l"(r) : "l"(a), "l"(b));
    return r;
}
__device__ __forceinline__ unsigned long long add2(unsigned long long a,
                                                   unsigned long long b) {
    unsigned long long r;
    asm("add.rn.f32x2 %0, %1, %2;" : "=l"(r) : "l"(a), "l"(b));
    return r;
}

// ---------------------------------------------------------------------------
// Kernel 1: build pair tables, fully parallel (one thread per pair).
// Inactive pairs get d2cut = -1 and are dropped by the tile cull in kernel 2
// (md2 >= 0 > -1). Survivor order == original pair order => deterministic.
// ---------------------------------------------------------------------------
__global__ __launch_bounds__(128)
void build_pairs(const float* __restrict__ X,
                 const float* __restrict__ aw,
                 const float* __restrict__ bw,
                 const int*   __restrict__ elements,
                 const int*   __restrict__ C_expand,
                 int npairs)
{
    const float LOG2E = 1.4426950408889634f;
    int j = blockIdx.x * 128 + threadIdx.x;
    if (j >= npairs) return;
    int a = j / NG;

    bool act = (elements[a] != 5) && (C_expand[a] == 1);
    float c = bw[j] * LOG2E;          // c < 0
    float w = aw[j];
    float px = X[a * 3 + 0];
    float py = X[a * 3 + 1];
    float pz = X[a * 3 + 2];

    g_cull[j] = make_float4(px, py, pz, act ? (T_CUT / (-c)) : -1.0f);
    g_pcA[j]  = make_float4(px, py, pz, c);
    g_pcB[j]  = make_float4(w, ex2f(0.5f * c), 0.25f * c, ex2f(2.0f * c));
}

// ---------------------------------------------------------------------------
// Kernel 2: density, fused. One 256-thread block per tile; warp w handles
// pair eighth w independently (cull + accumulate), then a deterministic
// fixed-order intra-block reduction and a direct coalesced store.
//
// Per-warp math: each lane owns one x-row (8 points); TWO-ANCHOR exp2
// recurrence with the two symmetric chains PACKED into f32x2 ops:
//   lane lo tracks points x0..x3 (anchor @ x0), lane hi x4..x7 (anchor @ x4)
//   r_i = 2^(c*dx_i + 0.25c),  r_{i+1} = r_i * q,  r_{i+4} = r_i * q4
// Anchors are direct EX2 (each point <= 1.5 A from its anchor => anchor
// magnitude >= 2^-111, no denormal flush).
// ---------------------------------------------------------------------------
__global__ __launch_bounds__(256)
void density_kernel(int npairs, float* __restrict__ out)
{
    __shared__ float4 s_pa[NWARP][CHUNK];             // px, py, pz, c
    __shared__ float4 s_pb[NWARP][CHUNK];             // w, q, c4, q4
    __shared__ float  s_acc[NWARP][32][TILE_X + 1];   // +1: bank padding

    int tid  = threadIdx.x;
    int lane = tid & 31;
    int wid  = tid >> 5;
    int bid  = blockIdx.x;
    int bx = bid % NBX;
    int by = (bid / NBX) % NBY;
    int bz = bid / (NBX * NBY);

    // Tile AABB in real coordinates
    float x_lo = (float)(bx * TILE_X) * SPACING;
    float y_lo = (float)(by * TILE_Y) * SPACING;
    float z_lo = (float)(bz * TILE_Z) * SPACING;
    float x_hi = x_lo + (float)(TILE_X - 1) * SPACING;
    float y_hi = y_lo + (float)(TILE_Y - 1) * SPACING;
    float z_hi = z_lo + (float)(TILE_Z - 1) * SPACING;

    // This lane's x-row: lane -> (ty in 0..7, tz in 0..3)
    int ty = lane & 7;
    int tz = lane >> 3;
    float gx0 = x_lo;
    float gy  = y_lo + (float)ty * SPACING;
    float gz  = z_lo + (float)tz * SPACING;

    // This warp's pair range
    int p_beg = (npairs * wid) / NWARP;
    int p_end = (npairs * (wid + 1)) / NWARP;

    // Packed accumulators: accp[i] = (sum @ x_i, sum @ x_{i+4})
    unsigned long long accp0 = 0ull, accp1 = 0ull, accp2 = 0ull, accp3 = 0ull;

    for (int c0 = p_beg; c0 < p_end; c0 += CHUNK) {
        int cend = p_end - c0;
        if (cend > CHUNK) cend = CHUNK;

        // ---- Fused cull + order-preserving compaction (per warp)
        int nsurv = 0;
#pragma unroll
        for (int r = 0; r < CHUNK / 32; r++) {
            int jl = r * 32 + lane;
            int j  = c0 + jl;
            bool sv = false;
            if (jl < cend) {
                float4 cd = g_cull[j];
                float dx = fmaxf(fmaxf(x_lo - cd.x, cd.x - x_hi), 0.0f);
                float dy = fmaxf(fmaxf(y_lo - cd.y, cd.y - y_hi), 0.0f);
                float dz = fmaxf(fmaxf(z_lo - cd.z, cd.z - z_hi), 0.0f);
                float md2 = fmaf(dx, dx, fmaf(dy, dy, dz * dz));
                sv = (md2 <= cd.w);
            }
            unsigned m = __ballot_sync(0xffffffffu, sv);
            if (sv) {
                int pos = nsurv + __popc(m & ((1u << lane) - 1u));
                s_pa[wid][pos] = g_pcA[j];
                s_pb[wid][pos] = g_pcB[j];
            }
            nsurv += __popc(m);
        }
        __syncwarp();

        // ---- Accumulate: packed two-anchor recurrence
        for (int s = 0; s < nsurv; s++) {
            float4 p = s_pa[wid][s];   // px, py, pz, c
            float4 v = s_pb[wid][s];   // w, q, c4, q4
            float dy = gy - p.y;
            float dz = gz - p.z;
            float s2 = fmaf(dy, dy, dz * dz);
            float dx0 = gx0 - p.x;
            float dx4 = dx0 + 2.0f;

            float e0 = v.x * ex2f(fmaf(dx0, dx0, s2) * p.w);   // anchor @ x0
            float e4 = v.x * ex2f(fmaf(dx4, dx4, s2) * p.w);   // anchor @ x4
            float r0 = ex2f(fmaf(p.w, dx0, v.z));              // ratio @ x0
            float r4 = r0 * v.w;                               // ratio @ x4

            unsigned long long ep = pk(e0, e4);
            unsigned long long rp = pk(r0, r4);
            unsigned long long qp = pk(v.y, v.y);

            accp0 = add2(accp0, ep);
            ep = mul2(ep, rp); rp = mul2(rp, qp);
            accp1 = add2(accp1, ep);
            ep = mul2(ep, rp); rp = mul2(rp, qp);
            accp2 = add2(accp2, ep);
            ep = mul2(ep, rp);
            accp3 = add2(accp3, ep);
        }
        __syncwarp();   // protect this warp's shared chunk before refill
    }

    // ---- Deposit per-warp accumulators (unpacked)
    {
        float a0, a4, a1, a5, a2, a6, a3, a7;
        unpk(a0, a4, accp0);
        unpk(a1, a5, accp1);
        unpk(a2, a6, accp2);
        unpk(a3, a7, accp3);
        s_acc[wid][lane][0] = a0;
        s_acc[wid][lane][1] = a1;
        s_acc[wid][lane][2] = a2;
        s_acc[wid][lane][3] = a3;
        s_acc[wid][lane][4] = a4;
        s_acc[wid][lane][5] = a5;
        s_acc[wid][lane][6] = a6;
        s_acc[wid][lane][7] = a7;
    }
    __syncthreads();

    // ---- Deterministic fixed-order reduction + direct coalesced store.
    // Thread t handles grid point: row l = t>>3 (32 rows), x index i = t&7.
    int l = tid >> 3;
    int i = tid & 7;
    int rty = l & 7;
    int rtz = l >> 3;
    int g0 = (bz * TILE_Z + rtz) * (GRID_NX * GRID_NY)
           + (by * TILE_Y + rty) * GRID_NX
           + bx * TILE_X + i;

    float r = s_acc[0][l][i];
#pragma unroll
    for (int w = 1; w < NWARP; w++)
        r += s_acc[w][l][i];
    out[g0] = r;
}

// ---------------------------------------------------------------------------
// Launch. Inputs (metadata order): X[800*3] f32, aw[800*6] f32, bw[800*6] f32,
// elements[800] i32, C_expand[800] i32, real_grid[110592*3] f32 (unused).
// Output: density[110592] f32.
// ---------------------------------------------------------------------------
extern "C" void kernel_launch(void* const* d_in, const int* in_sizes, int n_in,
                              void* d_out, int out_size)
{
    const float* X        = (const float*)d_in[0];
    const float* aw       = (const float*)d_in[1];
    const float* bw       = (const float*)d_in[2];
    const int*   elements = (const int*)d_in[3];
    const int*   C_expand = (const int*)d_in[4];
    float*       out      = (float*)d_out;

    int n_atoms = in_sizes[3];
    int npairs  = n_atoms * NG;

    build_pairs<<<(npairs + 127) / 128, 128>>>(X, aw, bw, elements, C_expand,
                                               npairs);

    density_kernel<<<N_TILES, 256>>>(npairs, out);
}